// round 2
// baseline (speedup 1.0000x reference)
#include <cuda_runtime.h>
#include <math.h>

#define Bn 4
#define Nn 6400
#define Dn 32
#define Gn 20
#define MARGINf 0.3f
#define EPSf 1e-12f
#define TILE 128
#define NEG_THREADS 128

// ---------------- scratch (device globals: no allocation allowed) ----------------
__device__ float g_coeffs[Bn * Nn * Dn];   // normalized coefficients, original order
__device__ float g_mcoeff[Bn * Nn * Dn];   // compacted fg coeffs, grouped by (gt, j asc)
__device__ int   g_midx[Bn * Nn];          // compact slot -> original j
__device__ unsigned char g_mgrp[Bn * Nn];  // compact slot -> group id
__device__ int   g_pig[Bn * Nn];           // original j -> position within its group list
__device__ float g_negs[Bn * Nn];          // original j -> max sim over different-group fg
__device__ int   g_cnt[Bn][Gn];
__device__ int   g_offs[Bn][Gn + 1];
__device__ double g_sum;
__device__ int    g_num;
__device__ int    g_gt64;   // 1 if target_gt_idx buffer is int64
__device__ int    g_fg32;   // 1 if fg_mask buffer is int32

// ---------------- dtype-robust accessors ----------------
__device__ __forceinline__ int get_gt(const void* p, int i) {
    return g_gt64 ? (int)((const long long*)p)[i] : ((const int*)p)[i];
}
__device__ __forceinline__ bool get_fg(const void* p, int i) {
    return g_fg32 ? (((const int*)p)[i] != 0) : (((const unsigned char*)p)[i] != 0);
}

// ---------------- kernels ----------------
__global__ void k_detect(const void* gt, const void* fg) {
    // gt: int64 iff high words of first 64 elements are all zero (values are 0..19)
    const int* w = (const int*)gt;
    int any = 0;
#pragma unroll
    for (int j = 0; j < 64; j++) any |= w[2 * j + 1];
    g_gt64 = (any == 0) ? 1 : 0;
    // fg: int32 iff bytes at offsets !=0 (mod 4) of first 64 elements are all zero
    const unsigned char* fb = (const unsigned char*)fg;
    int nb = 0;
#pragma unroll
    for (int j = 0; j < 64; j++) nb |= fb[4 * j + 1] | fb[4 * j + 2] | fb[4 * j + 3];
    g_fg32 = (nb == 0) ? 1 : 0;
    g_sum = 0.0;
    g_num = 0;
}

__global__ void k_norm(const float* __restrict__ pred) {
    int i = blockIdx.x * blockDim.x + threadIdx.x;
    if (i >= Bn * Nn) return;
    const float4* src = (const float4*)(pred + (size_t)i * Dn);
    float4 v[8];
    float ss = 0.f;
#pragma unroll
    for (int c = 0; c < 8; c++) {
        v[c] = src[c];
        ss += v[c].x * v[c].x + v[c].y * v[c].y + v[c].z * v[c].z + v[c].w * v[c].w;
    }
    float inv = 1.0f / fmaxf(sqrtf(ss), EPSf);
    float4* dst = (float4*)(g_coeffs + (size_t)i * Dn);
#pragma unroll
    for (int c = 0; c < 8; c++) {
        v[c].x *= inv; v[c].y *= inv; v[c].z *= inv; v[c].w *= inv;
        dst[c] = v[c];
    }
}

__global__ void k_hist(const void* __restrict__ gt, const void* __restrict__ fg) {
    int b = blockIdx.x;
    __shared__ int h[Gn];
    if (threadIdx.x < Gn) h[threadIdx.x] = 0;
    __syncthreads();
    for (int j = threadIdx.x; j < Nn; j += blockDim.x)
        if (get_fg(fg, b * Nn + j)) atomicAdd(&h[get_gt(gt, b * Nn + j)], 1);
    __syncthreads();
    if (threadIdx.x == 0) {
        int acc = 0;
        for (int g = 0; g < Gn; g++) { g_cnt[b][g] = h[g]; g_offs[b][g] = acc; acc += h[g]; }
        g_offs[b][Gn] = acc;
    }
}

// one warp per (group, batch): ordered compaction via ballot
__global__ void k_fill(const void* __restrict__ gt, const void* __restrict__ fg) {
    int b = blockIdx.y, g = blockIdx.x, lane = threadIdx.x;
    int base = g_offs[b][g];
    int cursor = base;
    for (int j0 = 0; j0 < Nn; j0 += 32) {
        int j = j0 + lane;
        bool m = get_fg(fg, b * Nn + j) && (get_gt(gt, b * Nn + j) == g);
        unsigned bal = __ballot_sync(0xffffffffu, m);
        if (m) {
            int pos = cursor + __popc(bal & ((1u << lane) - 1u));
            g_midx[b * Nn + pos] = j;
            g_mgrp[b * Nn + pos] = (unsigned char)g;
            g_pig[b * Nn + j]    = pos - base;
            const float4* s = (const float4*)(g_coeffs + ((size_t)b * Nn + j) * Dn);
            float4*       d = (float4*)(g_mcoeff + ((size_t)b * Nn + pos) * Dn);
#pragma unroll
            for (int c = 0; c < 8; c++) d[c] = s[c];
        }
        cursor += __popc(bal);
    }
}

__device__ __forceinline__ void dot_update(const float* __restrict__ ci,
                                           const float4* __restrict__ mp4,
                                           int gm, int gi, float& nm) {
    float d0 = 0.f, d1 = 0.f, d2 = 0.f, d3 = 0.f;
#pragma unroll
    for (int c = 0; c < 8; c++) {
        float4 v = mp4[c];
        d0 = fmaf(ci[4 * c + 0], v.x, d0);
        d1 = fmaf(ci[4 * c + 1], v.y, d1);
        d2 = fmaf(ci[4 * c + 2], v.z, d2);
        d3 = fmaf(ci[4 * c + 3], v.w, d3);
    }
    float dt = (d0 + d1) + (d2 + d3);
    if (gm != gi) nm = fmaxf(nm, dt);
}

// hot kernel: per fg anchor, max dot over fg candidates in a different group
__global__ void __launch_bounds__(NEG_THREADS) k_negmax() {
    int b = blockIdx.y;
    int A = g_offs[b][Gn];             // total fg in batch b
    int a = blockIdx.x * blockDim.x + threadIdx.x;
    if (blockIdx.x * blockDim.x >= A) return;   // whole-block early exit (uniform)
    bool act = a < A;

    float ci[Dn];
    int gi = -1;
    if (act) {
        const float4* s = (const float4*)(g_mcoeff + ((size_t)b * Nn + a) * Dn);
#pragma unroll
        for (int c = 0; c < 8; c++) {
            float4 v = s[c];
            ci[4 * c + 0] = v.x; ci[4 * c + 1] = v.y;
            ci[4 * c + 2] = v.z; ci[4 * c + 3] = v.w;
        }
        gi = g_mgrp[b * Nn + a];
    }

    float nm = -1e30f;
    __shared__ float sc[TILE * Dn];
    __shared__ int   sg[TILE];

    for (int t0 = 0; t0 < A; t0 += TILE) {
        int cnt = min(TILE, A - t0);
        __syncthreads();
        for (int idx = threadIdx.x; idx < cnt * 8; idx += blockDim.x) {
            int mm = idx >> 3, c = idx & 7;
            ((float4*)sc)[mm * 8 + c] =
                ((const float4*)(g_mcoeff + ((size_t)b * Nn + t0 + mm) * Dn))[c];
        }
        for (int idx = threadIdx.x; idx < cnt; idx += blockDim.x)
            sg[idx] = g_mgrp[b * Nn + t0 + idx];
        __syncthreads();
        if (act) {
            if (cnt == TILE) {
#pragma unroll 4
                for (int m = 0; m < TILE; m++)
                    dot_update(ci, (const float4*)(sc + m * Dn), sg[m], gi, nm);
            } else {
                for (int m = 0; m < cnt; m++)
                    dot_update(ci, (const float4*)(sc + m * Dn), sg[m], gi, nm);
            }
        }
    }
    if (act) g_negs[b * Nn + g_midx[b * Nn + a]] = nm;
}

__global__ void k_loss(const float* __restrict__ posr,
                       const void* __restrict__ gt,
                       const void* __restrict__ fg) {
    int i = blockIdx.x * blockDim.x + threadIdx.x;
    if (i >= Bn * Nn) return;
    if (!get_fg(fg, i)) return;
    int b = i / Nn;
    int g = get_gt(gt, i);
    int cnt = g_cnt[b][g];
    int np = cnt - 1;                      // positives = own-group fg minus self
    int A = g_offs[b][Gn];
    if (np < 1 || (A - cnt) <= 0) return;  // needs >=1 positive and >=1 negative

    float u = posr[i];
    int k = (int)floorf(u * (float)np);
    k = min(max(k, 0), np - 1);
    int p = g_pig[i];
    int slot = (k < p) ? k : k + 1;        // skip self in the ordered group list
    int jp = g_midx[b * Nn + g_offs[b][g] + slot];

    const float* ci = g_coeffs + (size_t)i * Dn;
    const float* cp = g_coeffs + ((size_t)b * Nn + jp) * Dn;
    float ss = 0.f;
#pragma unroll
    for (int c = 0; c < Dn; c++) {
        float dd = ci[c] - cp[c];
        ss = fmaf(dd, dd, ss);
    }
    float pos_d = sqrtf(ss + EPSf);

    float s = g_negs[i];
    float nd2 = 2.0f - 2.0f * s;
    if (nd2 < 0.f) nd2 = 0.f;
    float neg_d = sqrtf(nd2 + EPSf);

    float per = pos_d - neg_d + MARGINf;
    if (per < 0.f) per = 0.f;
    atomicAdd(&g_sum, (double)per);
    atomicAdd(&g_num, 1);
}

__global__ void k_out(float* out, int out_size) {
    float val = (g_num > 0) ? (float)(g_sum / (double)g_num) : 0.0f;
    for (int i = threadIdx.x; i < out_size; i += blockDim.x)
        out[i] = (i == 0) ? val : 0.0f;
}

// ---------------- launch ----------------
extern "C" void kernel_launch(void* const* d_in, const int* in_sizes, int n_in,
                              void* d_out, int out_size) {
    const float* pred = (const float*)d_in[0];
    const float* posr = (const float*)d_in[1];
    const void*  gt   = (const void*)d_in[2];
    const void*  fg   = (const void*)d_in[3];
    float* out = (float*)d_out;

    k_detect<<<1, 1>>>(gt, fg);
    k_norm<<<(Bn * Nn + 255) / 256, 256>>>(pred);
    k_hist<<<Bn, 256>>>(gt, fg);
    dim3 gf(Gn, Bn);
    k_fill<<<gf, 32>>>(gt, fg);
    dim3 g2((Nn + NEG_THREADS - 1) / NEG_THREADS, Bn);
    k_negmax<<<g2, NEG_THREADS>>>();
    k_loss<<<(Bn * Nn + 255) / 256, 256>>>(posr, gt, fg);
    k_out<<<1, 32>>>(out, out_size);
}

// round 3
// speedup vs baseline: 2.0784x; 2.0784x over previous
#include <cuda_runtime.h>
#include <math.h>

#define Bn 4
#define Nn 6400
#define Dn 32
#define Gn 20
#define NCH 50            // Nn / 128 chunks
#define MARGINf 0.3f
#define EPSf 1e-12f
#define TILE 128
#define NSPLIT 2

// ---------------- scratch (device globals) ----------------
__device__ float g_mcoeff[Bn * Nn * Dn];        // compacted fg coeffs, grouped by (gt, j asc)
__device__ unsigned char g_mgrp[Bn * Nn];       // compact slot -> group id
__device__ int   g_slot[Bn * Nn];               // original j -> within-batch compact slot (fg only)
__device__ float g_negsS[NSPLIT][Bn * Nn];      // per-split max sim over different-group fg
__device__ int   g_ccnt[Bn][NCH][Gn];
__device__ int   g_cbase[Bn][NCH][Gn];
__device__ int   g_cnt[Bn][Gn];
__device__ int   g_offs[Bn][Gn + 1];
__device__ double g_sum;
__device__ int    g_num;
__device__ int    g_gt64;
__device__ int    g_fg32;

// ---------------- dtype-robust accessors ----------------
__device__ __forceinline__ int get_gt(const void* p, int i) {
    return g_gt64 ? (int)((const long long*)p)[i] : ((const int*)p)[i];
}
__device__ __forceinline__ bool get_fg(const void* p, int i) {
    return g_fg32 ? (((const int*)p)[i] != 0) : (((const unsigned char*)p)[i] != 0);
}

// ---------------- packed f32x2 helpers ----------------
#define FMA2(d, a, b) asm("fma.rn.f32x2 %0, %1, %2, %0;" : "+l"(d) : "l"(a), "l"(b))
#define ADD2(d, a, b) asm("add.rn.f32x2 %0, %1, %2;" : "=l"(d) : "l"(a), "l"(b))

__device__ __forceinline__ float dot32(const unsigned long long* __restrict__ ci2,
                                       const float* __restrict__ cand) {
    const ulonglong2* p = (const ulonglong2*)cand;
    unsigned long long a0 = 0ull, a1 = 0ull, a2 = 0ull, a3 = 0ull;
#pragma unroll
    for (int k = 0; k < 4; k++) {
        ulonglong2 q0 = p[2 * k];
        ulonglong2 q1 = p[2 * k + 1];
        FMA2(a0, ci2[4 * k + 0], q0.x);
        FMA2(a1, ci2[4 * k + 1], q0.y);
        FMA2(a2, ci2[4 * k + 2], q1.x);
        FMA2(a3, ci2[4 * k + 3], q1.y);
    }
    unsigned long long s01, s23, s;
    ADD2(s01, a0, a1);
    ADD2(s23, a2, a3);
    ADD2(s, s01, s23);
    float lo, hi;
    asm("mov.b64 {%0,%1}, %2;" : "=f"(lo), "=f"(hi) : "l"(s));
    return lo + hi;
}

// ---------------- kernels ----------------
__global__ void k_detect(const void* gt, const void* fg) {
    const int* w = (const int*)gt;
    int any = 0;
#pragma unroll
    for (int j = 0; j < 64; j++) any |= w[2 * j + 1];
    g_gt64 = (any == 0) ? 1 : 0;
    const unsigned char* fb = (const unsigned char*)fg;
    int nb = 0;
#pragma unroll
    for (int j = 0; j < 64; j++) nb |= fb[4 * j + 1] | fb[4 * j + 2] | fb[4 * j + 3];
    g_fg32 = (nb == 0) ? 1 : 0;
    g_sum = 0.0;
    g_num = 0;
}

// Phase 1: per-(batch,chunk) group histogram
__global__ void __launch_bounds__(128) k_hist_chunk(const void* __restrict__ gt,
                                                    const void* __restrict__ fg) {
    int b = blockIdx.y, ch = blockIdx.x, t = threadIdx.x;
    __shared__ int h[Gn];
    if (t < Gn) h[t] = 0;
    __syncthreads();
    int j = ch * 128 + t;
    if (get_fg(fg, b * Nn + j)) atomicAdd(&h[get_gt(gt, b * Nn + j)], 1);
    __syncthreads();
    if (t < Gn) g_ccnt[b][ch][t] = h[t];
}

// Phase 2: prefix scans (tiny)
__global__ void __launch_bounds__(128) k_scan() {
    int t = threadIdx.x;
    if (t < Bn * Gn) {
        int b = t / Gn, g = t % Gn, run = 0;
        for (int ch = 0; ch < NCH; ch++) { g_cbase[b][ch][g] = run; run += g_ccnt[b][ch][g]; }
        g_cnt[b][g] = run;
    }
    __syncthreads();
    if (t < Bn) {
        int b = t, acc = 0;
        for (int g = 0; g < Gn; g++) { g_offs[b][g] = acc; acc += g_cnt[b][g]; }
        g_offs[b][Gn] = acc;
    }
    __syncthreads();
    if (t < Bn * Gn) {
        int b = t / Gn, g = t % Gn, o = g_offs[b][g];
        for (int ch = 0; ch < NCH; ch++) g_cbase[b][ch][g] += o;
    }
}

// Phase 3: placement + fused normalization (fg points only)
__global__ void __launch_bounds__(128) k_place(const float* __restrict__ pred,
                                               const void* __restrict__ gt,
                                               const void* __restrict__ fg) {
    int b = blockIdx.y, ch = blockIdx.x, t = threadIdx.x;
    int j = ch * 128 + t;
    bool m = get_fg(fg, b * Nn + j);
    int gv = m ? get_gt(gt, b * Nn + j) : -1;
    __shared__ signed char sgrp[128];
    sgrp[t] = (signed char)gv;
    __syncthreads();
    if (!m) return;
    int r = 0;
    for (int t2 = 0; t2 < t; t2++) r += (sgrp[t2] == gv);
    int pos = g_cbase[b][ch][gv] + r;
    g_mgrp[b * Nn + pos] = (unsigned char)gv;
    g_slot[b * Nn + j] = pos;

    const float4* s = (const float4*)(pred + ((size_t)b * Nn + j) * Dn);
    float4 v[8];
    float ss = 0.f;
#pragma unroll
    for (int c = 0; c < 8; c++) {
        v[c] = s[c];
        ss += v[c].x * v[c].x + v[c].y * v[c].y + v[c].z * v[c].z + v[c].w * v[c].w;
    }
    float inv = 1.0f / fmaxf(sqrtf(ss), EPSf);
    float4* d = (float4*)(g_mcoeff + ((size_t)b * Nn + pos) * Dn);
#pragma unroll
    for (int c = 0; c < 8; c++) {
        v[c].x *= inv; v[c].y *= inv; v[c].z *= inv; v[c].w *= inv;
        d[c] = v[c];
    }
}

// Hot kernel: per fg anchor (compact slot), max dot over different-group candidates.
// Candidates are group-sorted, so "different group" = outside [lo,hi) — per-tile branch.
__global__ void __launch_bounds__(128) k_negmax() {
    int b = blockIdx.y;
    int A = g_offs[b][Gn];
    if (blockIdx.x * 128 >= A) return;
    int a = blockIdx.x * 128 + threadIdx.x;
    bool act = a < A;

    int z = blockIdx.z;
    int half = (A + NSPLIT - 1) / NSPLIT;
    int cbeg = z * half;
    int cend = min(A, cbeg + half);

    unsigned long long ci2[16];
    int lo = 0, hi = 0;
    if (act) {
        const ulonglong2* s = (const ulonglong2*)(g_mcoeff + ((size_t)b * Nn + a) * Dn);
#pragma unroll
        for (int k = 0; k < 8; k++) { ulonglong2 q = s[k]; ci2[2 * k] = q.x; ci2[2 * k + 1] = q.y; }
        int gi = g_mgrp[b * Nn + a];
        lo = g_offs[b][gi];
        hi = g_offs[b][gi + 1];
    }

    float nm = -1e30f;
    __shared__ float sc[TILE * Dn];

    for (int t0 = cbeg; t0 < cend; t0 += TILE) {
        int cnt = min(TILE, cend - t0);
        __syncthreads();
        for (int idx = threadIdx.x; idx < cnt * 8; idx += 128) {
            int mm = idx >> 3, c = idx & 7;
            ((float4*)sc)[mm * 8 + c] =
                ((const float4*)(g_mcoeff + ((size_t)b * Nn + t0 + mm) * Dn))[c];
        }
        __syncthreads();
        if (act) {
            bool ovl = (hi > t0) && (lo < t0 + cnt);
            if (!ovl) {
#pragma unroll 4
                for (int m = 0; m < cnt; m++) {
                    float dt = dot32(ci2, sc + m * Dn);
                    nm = fmaxf(nm, dt);
                }
            } else {
#pragma unroll 4
                for (int m = 0; m < cnt; m++) {
                    float dt = dot32(ci2, sc + m * Dn);
                    int mg = t0 + m;
                    if (mg < lo || mg >= hi) nm = fmaxf(nm, dt);
                }
            }
        }
    }
    if (act) g_negsS[z][b * Nn + a] = nm;
}

__global__ void k_loss(const float* __restrict__ posr,
                       const void* __restrict__ gt,
                       const void* __restrict__ fg) {
    int i = blockIdx.x * blockDim.x + threadIdx.x;
    if (i >= Bn * Nn) return;
    if (!get_fg(fg, i)) return;
    int b = i / Nn;
    int g = get_gt(gt, i);
    int cnt = g_cnt[b][g];
    int np = cnt - 1;
    int A = g_offs[b][Gn];
    if (np < 1 || (A - cnt) <= 0) return;

    int slot = g_slot[i];
    int base = g_offs[b][g];
    int p = slot - base;

    float u = posr[i];
    int k = (int)floorf(u * (float)np);
    k = min(max(k, 0), np - 1);
    int sl = (k < p) ? k : k + 1;      // skip self in the ordered group list
    int jslot = base + sl;

    const float* ci = g_mcoeff + ((size_t)b * Nn + slot) * Dn;
    const float* cp = g_mcoeff + ((size_t)b * Nn + jslot) * Dn;
    float ss = 0.f;
#pragma unroll
    for (int c = 0; c < Dn; c++) {
        float dd = ci[c] - cp[c];
        ss = fmaf(dd, dd, ss);
    }
    float pos_d = sqrtf(ss + EPSf);

    float s = fmaxf(g_negsS[0][b * Nn + slot], g_negsS[1][b * Nn + slot]);
    float nd2 = 2.0f - 2.0f * s;
    if (nd2 < 0.f) nd2 = 0.f;
    float neg_d = sqrtf(nd2 + EPSf);

    float per = pos_d - neg_d + MARGINf;
    if (per < 0.f) per = 0.f;
    atomicAdd(&g_sum, (double)per);
    atomicAdd(&g_num, 1);
}

__global__ void k_out(float* out, int out_size) {
    float val = (g_num > 0) ? (float)(g_sum / (double)g_num) : 0.0f;
    for (int i = threadIdx.x; i < out_size; i += blockDim.x)
        out[i] = (i == 0) ? val : 0.0f;
}

// ---------------- launch ----------------
extern "C" void kernel_launch(void* const* d_in, const int* in_sizes, int n_in,
                              void* d_out, int out_size) {
    const float* pred = (const float*)d_in[0];
    const float* posr = (const float*)d_in[1];
    const void*  gt   = (const void*)d_in[2];
    const void*  fg   = (const void*)d_in[3];
    float* out = (float*)d_out;

    k_detect<<<1, 1>>>(gt, fg);
    dim3 gc(NCH, Bn);
    k_hist_chunk<<<gc, 128>>>(gt, fg);
    k_scan<<<1, 128>>>();
    k_place<<<gc, 128>>>(pred, gt, fg);
    dim3 gn((Nn + 127) / 128, Bn, NSPLIT);
    k_negmax<<<gn, 128>>>();
    k_loss<<<(Bn * Nn + 255) / 256, 256>>>(posr, gt, fg);
    k_out<<<1, 32>>>(out, out_size);
}

// round 4
// speedup vs baseline: 2.4511x; 1.1793x over previous
#include <cuda_runtime.h>
#include <math.h>

#define Bn 4
#define Nn 6400
#define Dn 32
#define Gn 20
#define NCH 50            // Nn / 128 chunks
#define MARGINf 0.3f
#define EPSf 1e-12f
#define TILE 128
#define NSPLIT 3

// ---------------- scratch (device globals) ----------------
__device__ float g_mcoeff[Bn * Nn * Dn];        // compacted fg coeffs, grouped by (gt, j asc)
__device__ unsigned char g_mgrp[Bn * Nn];       // compact slot -> group id
__device__ int   g_slot[Bn * Nn];               // original j -> within-batch compact slot (fg only)
__device__ float g_negsS[NSPLIT][Bn * Nn];      // per-split max sim over different-group fg
__device__ int   g_ccnt[Bn][NCH][Gn];
__device__ int   g_cbase[Bn][NCH][Gn];
__device__ int   g_cnt[Bn][Gn];
__device__ int   g_offs[Bn][Gn + 1];
__device__ double g_sum;
__device__ int    g_num;
__device__ int    g_gt64;
__device__ int    g_fg32;

// ---------------- dtype-robust accessors ----------------
__device__ __forceinline__ int get_gt(const void* p, int i) {
    return g_gt64 ? (int)((const long long*)p)[i] : ((const int*)p)[i];
}
__device__ __forceinline__ bool get_fg(const void* p, int i) {
    return g_fg32 ? (((const int*)p)[i] != 0) : (((const unsigned char*)p)[i] != 0);
}

// ---------------- packed f32x2 helpers ----------------
#define FMA2(d, a, b) asm("fma.rn.f32x2 %0, %1, %2, %0;" : "+l"(d) : "l"(a), "l"(b))
#define ADD2(d, a, b) asm("add.rn.f32x2 %0, %1, %2;" : "=l"(d) : "l"(a), "l"(b))

// one candidate: 16 FMA2 on 4 packed accumulators; temps live briefly (no spills)
__device__ __forceinline__ float dot32(const unsigned long long* __restrict__ ci2,
                                       const float* __restrict__ cand) {
    const ulonglong2* p = (const ulonglong2*)cand;
    unsigned long long a0 = 0ull, a1 = 0ull, a2 = 0ull, a3 = 0ull;
#pragma unroll
    for (int k = 0; k < 4; k++) {
        ulonglong2 q0 = p[2 * k];
        ulonglong2 q1 = p[2 * k + 1];
        FMA2(a0, ci2[4 * k + 0], q0.x);
        FMA2(a1, ci2[4 * k + 1], q0.y);
        FMA2(a2, ci2[4 * k + 2], q1.x);
        FMA2(a3, ci2[4 * k + 3], q1.y);
    }
    unsigned long long s01, s23, s;
    ADD2(s01, a0, a1);
    ADD2(s23, a2, a3);
    ADD2(s, s01, s23);
    float lo, hi;
    asm("mov.b64 {%0,%1}, %2;" : "=f"(lo), "=f"(hi) : "l"(s));
    return lo + hi;
}

// ---------------- kernels ----------------
__global__ void k_detect(const void* gt, const void* fg) {
    const int* w = (const int*)gt;
    int any = 0;
#pragma unroll
    for (int j = 0; j < 64; j++) any |= w[2 * j + 1];
    g_gt64 = (any == 0) ? 1 : 0;
    const unsigned char* fb = (const unsigned char*)fg;
    int nb = 0;
#pragma unroll
    for (int j = 0; j < 64; j++) nb |= fb[4 * j + 1] | fb[4 * j + 2] | fb[4 * j + 3];
    g_fg32 = (nb == 0) ? 1 : 0;
    g_sum = 0.0;
    g_num = 0;
}

// Phase 1: per-(batch,chunk) group histogram
__global__ void __launch_bounds__(128) k_hist_chunk(const void* __restrict__ gt,
                                                    const void* __restrict__ fg) {
    int b = blockIdx.y, ch = blockIdx.x, t = threadIdx.x;
    __shared__ int h[Gn];
    if (t < Gn) h[t] = 0;
    __syncthreads();
    int j = ch * 128 + t;
    if (get_fg(fg, b * Nn + j)) atomicAdd(&h[get_gt(gt, b * Nn + j)], 1);
    __syncthreads();
    if (t < Gn) g_ccnt[b][ch][t] = h[t];
}

// Phase 2: prefix scans (tiny)
__global__ void __launch_bounds__(128) k_scan() {
    int t = threadIdx.x;
    if (t < Bn * Gn) {
        int b = t / Gn, g = t % Gn, run = 0;
        for (int ch = 0; ch < NCH; ch++) { g_cbase[b][ch][g] = run; run += g_ccnt[b][ch][g]; }
        g_cnt[b][g] = run;
    }
    __syncthreads();
    if (t < Bn) {
        int b = t, acc = 0;
        for (int g = 0; g < Gn; g++) { g_offs[b][g] = acc; acc += g_cnt[b][g]; }
        g_offs[b][Gn] = acc;
    }
    __syncthreads();
    if (t < Bn * Gn) {
        int b = t / Gn, g = t % Gn, o = g_offs[b][g];
        for (int ch = 0; ch < NCH; ch++) g_cbase[b][ch][g] += o;
    }
}

// Phase 3: placement + fused normalization (fg points only)
__global__ void __launch_bounds__(128) k_place(const float* __restrict__ pred,
                                               const void* __restrict__ gt,
                                               const void* __restrict__ fg) {
    int b = blockIdx.y, ch = blockIdx.x, t = threadIdx.x;
    int j = ch * 128 + t;
    bool m = get_fg(fg, b * Nn + j);
    int gv = m ? get_gt(gt, b * Nn + j) : -1;
    __shared__ signed char sgrp[128];
    sgrp[t] = (signed char)gv;
    __syncthreads();
    if (!m) return;
    int r = 0;
    for (int t2 = 0; t2 < t; t2++) r += (sgrp[t2] == gv);
    int pos = g_cbase[b][ch][gv] + r;
    g_mgrp[b * Nn + pos] = (unsigned char)gv;
    g_slot[b * Nn + j] = pos;

    const float4* s = (const float4*)(pred + ((size_t)b * Nn + j) * Dn);
    float4 v[8];
    float ss = 0.f;
#pragma unroll
    for (int c = 0; c < 8; c++) {
        v[c] = s[c];
        ss += v[c].x * v[c].x + v[c].y * v[c].y + v[c].z * v[c].z + v[c].w * v[c].w;
    }
    float inv = 1.0f / fmaxf(sqrtf(ss), EPSf);
    float4* d = (float4*)(g_mcoeff + ((size_t)b * Nn + pos) * Dn);
#pragma unroll
    for (int c = 0; c < 8; c++) {
        v[c].x *= inv; v[c].y *= inv; v[c].z *= inv; v[c].w *= inv;
        d[c] = v[c];
    }
}

// Hot kernel: per fg anchor (compact slot), max dot over different-group candidates.
// Candidates are group-sorted, so "different group" = outside [lo,hi) — per-tile branch.
// __launch_bounds__(128,4) caps regs at 128/thread: no local-memory spills.
__global__ void __launch_bounds__(128, 4) k_negmax() {
    int b = blockIdx.y;
    int A = g_offs[b][Gn];
    if (blockIdx.x * 128 >= A) return;
    int a = blockIdx.x * 128 + threadIdx.x;
    bool act = a < A;

    int z = blockIdx.z;
    int part = (A + NSPLIT - 1) / NSPLIT;
    int cbeg = z * part;
    int cend = min(A, cbeg + part);

    unsigned long long ci2[16];
    int lo = 0, hi = 0;
    if (act) {
        const ulonglong2* s = (const ulonglong2*)(g_mcoeff + ((size_t)b * Nn + a) * Dn);
#pragma unroll
        for (int k = 0; k < 8; k++) { ulonglong2 q = s[k]; ci2[2 * k] = q.x; ci2[2 * k + 1] = q.y; }
        int gi = g_mgrp[b * Nn + a];
        lo = g_offs[b][gi];
        hi = g_offs[b][gi + 1];
    }

    float nm = -1e30f;
    __shared__ float sc[TILE * Dn];

    for (int t0 = cbeg; t0 < cend; t0 += TILE) {
        int cnt = min(TILE, cend - t0);
        __syncthreads();
        for (int idx = threadIdx.x; idx < cnt * 8; idx += 128) {
            int mm = idx >> 3, c = idx & 7;
            ((float4*)sc)[mm * 8 + c] =
                ((const float4*)(g_mcoeff + ((size_t)b * Nn + t0 + mm) * Dn))[c];
        }
        __syncthreads();
        if (act) {
            bool ovl = (hi > t0) && (lo < t0 + cnt);
            if (!ovl) {
#pragma unroll 2
                for (int m = 0; m < cnt; m++) {
                    float dt = dot32(ci2, sc + m * Dn);
                    nm = fmaxf(nm, dt);
                }
            } else {
#pragma unroll 2
                for (int m = 0; m < cnt; m++) {
                    float dt = dot32(ci2, sc + m * Dn);
                    int mg = t0 + m;
                    if (mg < lo || mg >= hi) nm = fmaxf(nm, dt);
                }
            }
        }
    }
    if (act) g_negsS[z][b * Nn + a] = nm;
}

__global__ void __launch_bounds__(256) k_loss(const float* __restrict__ posr,
                                              const void* __restrict__ gt,
                                              const void* __restrict__ fg) {
    int i = blockIdx.x * blockDim.x + threadIdx.x;
    float per = 0.f;
    int cntv = 0;
    if (i < Bn * Nn && get_fg(fg, i)) {
        int b = i / Nn;
        int g = get_gt(gt, i);
        int cnt = g_cnt[b][g];
        int np = cnt - 1;
        int A = g_offs[b][Gn];
        if (np >= 1 && (A - cnt) > 0) {
            int slot = g_slot[i];
            int base = g_offs[b][g];
            int p = slot - base;

            float u = posr[i];
            int k = (int)floorf(u * (float)np);
            k = min(max(k, 0), np - 1);
            int sl = (k < p) ? k : k + 1;      // skip self in the ordered group list
            int jslot = base + sl;

            const float* ci = g_mcoeff + ((size_t)b * Nn + slot) * Dn;
            const float* cp = g_mcoeff + ((size_t)b * Nn + jslot) * Dn;
            float ss = 0.f;
#pragma unroll
            for (int c = 0; c < Dn; c++) {
                float dd = ci[c] - cp[c];
                ss = fmaf(dd, dd, ss);
            }
            float pos_d = sqrtf(ss + EPSf);

            float s = g_negsS[0][b * Nn + slot];
#pragma unroll
            for (int zz = 1; zz < NSPLIT; zz++) s = fmaxf(s, g_negsS[zz][b * Nn + slot]);
            float nd2 = 2.0f - 2.0f * s;
            if (nd2 < 0.f) nd2 = 0.f;
            float neg_d = sqrtf(nd2 + EPSf);

            per = pos_d - neg_d + MARGINf;
            if (per < 0.f) per = 0.f;
            cntv = 1;
        }
    }
    // block reduction (double for determinism-insensitive accuracy)
    double pv = (double)per;
#pragma unroll
    for (int o = 16; o > 0; o >>= 1) {
        pv  += __shfl_down_sync(0xffffffffu, pv, o);
        cntv += __shfl_down_sync(0xffffffffu, cntv, o);
    }
    __shared__ double sp[8];
    __shared__ int    sn[8];
    int w = threadIdx.x >> 5, l = threadIdx.x & 31;
    if (l == 0) { sp[w] = pv; sn[w] = cntv; }
    __syncthreads();
    if (w == 0) {
        double v = (l < 8) ? sp[l] : 0.0;
        int    n = (l < 8) ? sn[l] : 0;
#pragma unroll
        for (int o = 4; o > 0; o >>= 1) {
            v += __shfl_down_sync(0xffffffffu, v, o);
            n += __shfl_down_sync(0xffffffffu, n, o);
        }
        if (l == 0 && (v != 0.0 || n != 0)) {
            atomicAdd(&g_sum, v);
            atomicAdd(&g_num, n);
        }
    }
}

__global__ void k_out(float* out, int out_size) {
    float val = (g_num > 0) ? (float)(g_sum / (double)g_num) : 0.0f;
    for (int i = threadIdx.x; i < out_size; i += blockDim.x)
        out[i] = (i == 0) ? val : 0.0f;
}

// ---------------- launch ----------------
extern "C" void kernel_launch(void* const* d_in, const int* in_sizes, int n_in,
                              void* d_out, int out_size) {
    const float* pred = (const float*)d_in[0];
    const float* posr = (const float*)d_in[1];
    const void*  gt   = (const void*)d_in[2];
    const void*  fg   = (const void*)d_in[3];
    float* out = (float*)d_out;

    k_detect<<<1, 1>>>(gt, fg);
    dim3 gc(NCH, Bn);
    k_hist_chunk<<<gc, 128>>>(gt, fg);
    k_scan<<<1, 128>>>();
    k_place<<<gc, 128>>>(pred, gt, fg);
    dim3 gn((Nn + 127) / 128, Bn, NSPLIT);
    k_negmax<<<gn, 128>>>();
    k_loss<<<(Bn * Nn + 255) / 256, 256>>>(posr, gt, fg);
    k_out<<<1, 32>>>(out, out_size);
}

// round 5
// speedup vs baseline: 3.0130x; 1.2292x over previous
#include <cuda_runtime.h>
#include <math.h>

#define Bn 4
#define Nn 6400
#define Dn 32
#define Gn 20
#define NCH 50            // Nn / 128 chunks
#define MARGINf 0.3f
#define EPSf 1e-12f
#define TILE 128
#define NSPLIT 6

// ---------------- scratch (device globals) ----------------
__device__ float g_mcoeff[Bn * Nn * Dn];        // compacted fg coeffs, grouped by (gt, j asc)
__device__ unsigned char g_mgrp[Bn * Nn];       // compact slot -> group id
__device__ int   g_slot[Bn * Nn];               // original j -> within-batch compact slot (fg only)
__device__ float g_negsS[NSPLIT][Bn * Nn];      // per-split max sim over different-group fg
__device__ int   g_ccnt[Bn][NCH][Gn];
__device__ int   g_cbase[Bn][NCH][Gn];
__device__ int   g_cnt[Bn][Gn];
__device__ int   g_offs[Bn][Gn + 1];
__device__ double g_sum;
__device__ int    g_num;

// ---------------- inline dtype detection (deterministic, same result everywhere) ----
// gt is int64 iff the high words of its first 64 elements (values 0..19) are all zero.
// fg is int32 iff bytes at offsets !=0 (mod 4) of its first 64 elements are all zero.
__device__ __forceinline__ void detect_flags(const void* gt, const void* fg,
                                             int& gt64, int& fg32) {
    const int* w = (const int*)gt;
    int any = 0;
#pragma unroll 8
    for (int j = 0; j < 64; j++) any |= w[2 * j + 1];
    gt64 = (any == 0) ? 1 : 0;
    const unsigned char* fb = (const unsigned char*)fg;
    int nb = 0;
#pragma unroll 8
    for (int j = 0; j < 64; j++) nb |= fb[4 * j + 1] | fb[4 * j + 2] | fb[4 * j + 3];
    fg32 = (nb == 0) ? 1 : 0;
}

__device__ __forceinline__ int get_gt(const void* p, int i, int gt64) {
    return gt64 ? (int)((const long long*)p)[i] : ((const int*)p)[i];
}
__device__ __forceinline__ bool get_fg(const void* p, int i, int fg32) {
    return fg32 ? (((const int*)p)[i] != 0) : (((const unsigned char*)p)[i] != 0);
}

// ---------------- packed f32x2 helpers ----------------
#define FMA2(d, a, b) asm("fma.rn.f32x2 %0, %1, %2, %0;" : "+l"(d) : "l"(a), "l"(b))
#define ADD2(d, a, b) asm("add.rn.f32x2 %0, %1, %2;" : "=l"(d) : "l"(a), "l"(b))

// one candidate: 16 FMA2 on 2 packed accumulators
__device__ __forceinline__ float dot32(const unsigned long long* __restrict__ ci2,
                                       const float* __restrict__ cand) {
    const ulonglong2* p = (const ulonglong2*)cand;
    unsigned long long a0 = 0ull, a1 = 0ull;
#pragma unroll
    for (int k = 0; k < 4; k++) {
        ulonglong2 q0 = p[2 * k];
        ulonglong2 q1 = p[2 * k + 1];
        FMA2(a0, ci2[4 * k + 0], q0.x);
        FMA2(a1, ci2[4 * k + 1], q0.y);
        FMA2(a0, ci2[4 * k + 2], q1.x);
        FMA2(a1, ci2[4 * k + 3], q1.y);
    }
    unsigned long long s;
    ADD2(s, a0, a1);
    float lo, hi;
    asm("mov.b64 {%0,%1}, %2;" : "=f"(lo), "=f"(hi) : "l"(s));
    return lo + hi;
}

// ---------------- kernels ----------------
// Launch #1: per-(batch,chunk) group histogram (inline dtype detect via shared bcast)
__global__ void __launch_bounds__(128) k_hist_chunk(const void* __restrict__ gt,
                                                    const void* __restrict__ fg) {
    int b = blockIdx.y, ch = blockIdx.x, t = threadIdx.x;
    __shared__ int h[Gn];
    __shared__ int fl[2];
    if (t == 0) { int a, c; detect_flags(gt, fg, a, c); fl[0] = a; fl[1] = c; }
    if (t < Gn) h[t] = 0;
    __syncthreads();
    int gt64 = fl[0], fg32 = fl[1];
    int j = ch * 128 + t;
    if (get_fg(fg, b * Nn + j, fg32)) atomicAdd(&h[get_gt(gt, b * Nn + j, gt64)], 1);
    __syncthreads();
    if (t < Gn) g_ccnt[b][ch][t] = h[t];
}

// Launch #2: prefix scans (tiny) + accumulator init
__global__ void __launch_bounds__(128) k_scan() {
    int t = threadIdx.x;
    if (t == 0) { g_sum = 0.0; g_num = 0; }
    if (t < Bn * Gn) {
        int b = t / Gn, g = t % Gn, run = 0;
        for (int ch = 0; ch < NCH; ch++) { g_cbase[b][ch][g] = run; run += g_ccnt[b][ch][g]; }
        g_cnt[b][g] = run;
    }
    __syncthreads();
    if (t < Bn) {
        int b = t, acc = 0;
        for (int g = 0; g < Gn; g++) { g_offs[b][g] = acc; acc += g_cnt[b][g]; }
        g_offs[b][Gn] = acc;
    }
    __syncthreads();
    if (t < Bn * Gn) {
        int b = t / Gn, g = t % Gn, o = g_offs[b][g];
        for (int ch = 0; ch < NCH; ch++) g_cbase[b][ch][g] += o;
    }
}

// Launch #3: placement + fused normalization (fg points only)
__global__ void __launch_bounds__(128) k_place(const float* __restrict__ pred,
                                               const void* __restrict__ gt,
                                               const void* __restrict__ fg) {
    int b = blockIdx.y, ch = blockIdx.x, t = threadIdx.x;
    __shared__ signed char sgrp[128];
    __shared__ int fl[2];
    if (t == 0) { int a, c; detect_flags(gt, fg, a, c); fl[0] = a; fl[1] = c; }
    __syncthreads();
    int gt64 = fl[0], fg32 = fl[1];
    int j = ch * 128 + t;
    bool m = get_fg(fg, b * Nn + j, fg32);
    int gv = m ? get_gt(gt, b * Nn + j, gt64) : -1;
    sgrp[t] = (signed char)gv;
    __syncthreads();
    if (!m) return;
    int r = 0;
    for (int t2 = 0; t2 < t; t2++) r += (sgrp[t2] == gv);
    int pos = g_cbase[b][ch][gv] + r;
    g_mgrp[b * Nn + pos] = (unsigned char)gv;
    g_slot[b * Nn + j] = pos;

    const float4* s = (const float4*)(pred + ((size_t)b * Nn + j) * Dn);
    float4 v[8];
    float ss = 0.f;
#pragma unroll
    for (int c = 0; c < 8; c++) {
        v[c] = s[c];
        ss += v[c].x * v[c].x + v[c].y * v[c].y + v[c].z * v[c].z + v[c].w * v[c].w;
    }
    float inv = 1.0f / fmaxf(sqrtf(ss), EPSf);
    float4* d = (float4*)(g_mcoeff + ((size_t)b * Nn + pos) * Dn);
#pragma unroll
    for (int c = 0; c < 8; c++) {
        v[c].x *= inv; v[c].y *= inv; v[c].z *= inv; v[c].w *= inv;
        d[c] = v[c];
    }
}

// Launch #4 (ncu-profiled slot): per fg anchor, max dot over different-group candidates.
// Candidates are group-sorted, so "different group" = outside [lo,hi) — per-tile branch.
__global__ void __launch_bounds__(128, 4) k_negmax() {
    int b = blockIdx.y;
    int A = g_offs[b][Gn];
    if (blockIdx.x * 128 >= A) return;
    int a = blockIdx.x * 128 + threadIdx.x;
    bool act = a < A;

    int z = blockIdx.z;
    int part = (A + NSPLIT - 1) / NSPLIT;
    int cbeg = z * part;
    int cend = min(A, cbeg + part);

    unsigned long long ci2[16];
    int lo = 0, hi = 0;
    if (act) {
        const ulonglong2* s = (const ulonglong2*)(g_mcoeff + ((size_t)b * Nn + a) * Dn);
#pragma unroll
        for (int k = 0; k < 8; k++) { ulonglong2 q = s[k]; ci2[2 * k] = q.x; ci2[2 * k + 1] = q.y; }
        int gi = g_mgrp[b * Nn + a];
        lo = g_offs[b][gi];
        hi = g_offs[b][gi + 1];
    }

    float nm = -1e30f;
    __shared__ float sc[TILE * Dn];

    for (int t0 = cbeg; t0 < cend; t0 += TILE) {
        int cnt = min(TILE, cend - t0);
        __syncthreads();
        for (int idx = threadIdx.x; idx < cnt * 8; idx += 128) {
            int mm = idx >> 3, c = idx & 7;
            ((float4*)sc)[mm * 8 + c] =
                ((const float4*)(g_mcoeff + ((size_t)b * Nn + t0 + mm) * Dn))[c];
        }
        __syncthreads();
        if (act) {
            bool ovl = (hi > t0) && (lo < t0 + cnt);
            if (!ovl) {
#pragma unroll 2
                for (int m = 0; m < cnt; m++) {
                    float dt = dot32(ci2, sc + m * Dn);
                    nm = fmaxf(nm, dt);
                }
            } else {
#pragma unroll 2
                for (int m = 0; m < cnt; m++) {
                    float dt = dot32(ci2, sc + m * Dn);
                    int mg = t0 + m;
                    if (mg < lo || mg >= hi) nm = fmaxf(nm, dt);
                }
            }
        }
    }
    if (act) g_negsS[z][b * Nn + a] = nm;
}

// Launch #5: per-anchor triplet loss + block-level reduction
__global__ void __launch_bounds__(256) k_loss(const float* __restrict__ posr,
                                              const void* __restrict__ gt,
                                              const void* __restrict__ fg) {
    __shared__ int fl[2];
    if (threadIdx.x == 0) { int a, c; detect_flags(gt, fg, a, c); fl[0] = a; fl[1] = c; }
    __syncthreads();
    int gt64 = fl[0], fg32 = fl[1];

    int i = blockIdx.x * blockDim.x + threadIdx.x;
    float per = 0.f;
    int cntv = 0;
    if (i < Bn * Nn && get_fg(fg, i, fg32)) {
        int b = i / Nn;
        int g = get_gt(gt, i, gt64);
        int cnt = g_cnt[b][g];
        int np = cnt - 1;
        int A = g_offs[b][Gn];
        if (np >= 1 && (A - cnt) > 0) {
            int slot = g_slot[i];
            int base = g_offs[b][g];
            int p = slot - base;

            float u = posr[i];
            int k = (int)floorf(u * (float)np);
            k = min(max(k, 0), np - 1);
            int sl = (k < p) ? k : k + 1;      // skip self in the ordered group list
            int jslot = base + sl;

            const float* ci = g_mcoeff + ((size_t)b * Nn + slot) * Dn;
            const float* cp = g_mcoeff + ((size_t)b * Nn + jslot) * Dn;
            float ss = 0.f;
#pragma unroll
            for (int c = 0; c < Dn; c++) {
                float dd = ci[c] - cp[c];
                ss = fmaf(dd, dd, ss);
            }
            float pos_d = sqrtf(ss + EPSf);

            float s = g_negsS[0][b * Nn + slot];
#pragma unroll
            for (int zz = 1; zz < NSPLIT; zz++) s = fmaxf(s, g_negsS[zz][b * Nn + slot]);
            float nd2 = 2.0f - 2.0f * s;
            if (nd2 < 0.f) nd2 = 0.f;
            float neg_d = sqrtf(nd2 + EPSf);

            per = pos_d - neg_d + MARGINf;
            if (per < 0.f) per = 0.f;
            cntv = 1;
        }
    }
    double pv = (double)per;
#pragma unroll
    for (int o = 16; o > 0; o >>= 1) {
        pv   += __shfl_down_sync(0xffffffffu, pv, o);
        cntv += __shfl_down_sync(0xffffffffu, cntv, o);
    }
    __shared__ double sp[8];
    __shared__ int    sn[8];
    int w = threadIdx.x >> 5, l = threadIdx.x & 31;
    if (l == 0) { sp[w] = pv; sn[w] = cntv; }
    __syncthreads();
    if (w == 0) {
        double v = (l < 8) ? sp[l] : 0.0;
        int    n = (l < 8) ? sn[l] : 0;
#pragma unroll
        for (int o = 4; o > 0; o >>= 1) {
            v += __shfl_down_sync(0xffffffffu, v, o);
            n += __shfl_down_sync(0xffffffffu, n, o);
        }
        if (l == 0 && (v != 0.0 || n != 0)) {
            atomicAdd(&g_sum, v);
            atomicAdd(&g_num, n);
        }
    }
}

// Launch #6: finalize
__global__ void k_out(float* out, int out_size) {
    float val = (g_num > 0) ? (float)(g_sum / (double)g_num) : 0.0f;
    for (int i = threadIdx.x; i < out_size; i += blockDim.x)
        out[i] = (i == 0) ? val : 0.0f;
}

// ---------------- launch ----------------
extern "C" void kernel_launch(void* const* d_in, const int* in_sizes, int n_in,
                              void* d_out, int out_size) {
    const float* pred = (const float*)d_in[0];
    const float* posr = (const float*)d_in[1];
    const void*  gt   = (const void*)d_in[2];
    const void*  fg   = (const void*)d_in[3];
    float* out = (float*)d_out;

    dim3 gc(NCH, Bn);
    k_hist_chunk<<<gc, 128>>>(gt, fg);
    k_scan<<<1, 128>>>();
    k_place<<<gc, 128>>>(pred, gt, fg);
    dim3 gn((Nn + 127) / 128, Bn, NSPLIT);
    k_negmax<<<gn, 128>>>();
    k_loss<<<(Bn * Nn + 255) / 256, 256>>>(posr, gt, fg);
    k_out<<<1, 32>>>(out, out_size);
}

// round 8
// speedup vs baseline: 5.1813x; 1.7196x over previous
#include <cuda_runtime.h>
#include <cuda_bf16.h>
#include <math.h>
#include <stdint.h>

#define Bn 4
#define Nn 6400
#define Dn 32
#define Gn 20
#define NCH 50            // Nn / 128 chunks
#define MARGINf 0.3f
#define EPSf 1e-12f
#define MT 64             // anchors per block (4 warps x m16)
#define NT 128            // candidate tile rows
#define NSPLIT 3
#define BSTRIDE 208       // smem bytes per candidate row (192B data + 16B pad)
#define SMEM_NEG (NT * BSTRIDE)

// ---------------- scratch (device globals) ----------------
__device__ float    g_mcoeff[Bn * Nn * Dn];  // compacted fp32 coeffs (for pos_d)
__device__ uint32_t g_ea[Bn * Nn * 48];      // anchor-ext rows [hi|hi|lo], 96 bf16 = 48 u32
__device__ uint4    g_eb4[Bn * Nn * 12];     // cand-ext rows [hi|lo|hi], 192B = 12 u4
__device__ unsigned char g_mgrp[Bn * Nn];    // compact slot -> group id
__device__ int      g_slot[Bn * Nn];         // original j -> compact slot
__device__ float    g_negS[NSPLIT][Bn * Nn]; // per-split max sim over different-group fg
__device__ int      g_ccnt[Bn][NCH][Gn];
__device__ int      g_cbase[Bn][NCH][Gn];
__device__ int      g_cnt[Bn][Gn];
__device__ int      g_offs[Bn][Gn + 1];
__device__ double   g_sum;
__device__ int      g_num;
__device__ int      g_done;

// ---------------- dtype detection (warp-parallel, deterministic) ----------------
// gt is int64 iff high words of first 64 elements (values 0..19) are all zero.
// fg is int32 iff bytes at offsets !=0 (mod 4) of first 64 elements are all zero.
__device__ __forceinline__ void detect_warp(const void* gt, const void* fg,
                                            int t, int* fl) {
    if (t < 32) {
        const int* w = (const int*)gt;
        int any = w[2 * t + 1] | w[2 * (t + 32) + 1];
        const uchar4* f4 = (const uchar4*)fg;
        uchar4 q0 = f4[t], q1 = f4[t + 32];
        int nb = q0.y | q0.z | q0.w | q1.y | q1.z | q1.w;
        unsigned b1 = __ballot_sync(0xffffffffu, any != 0);
        unsigned b2 = __ballot_sync(0xffffffffu, nb != 0);
        if (t == 0) { fl[0] = (b1 == 0) ? 1 : 0; fl[1] = (b2 == 0) ? 1 : 0; }
    }
}
__device__ __forceinline__ int get_gt(const void* p, int i, int gt64) {
    return gt64 ? (int)((const long long*)p)[i] : ((const int*)p)[i];
}
__device__ __forceinline__ bool get_fg(const void* p, int i, int fg32) {
    return fg32 ? (((const int*)p)[i] != 0) : (((const unsigned char*)p)[i] != 0);
}

// ---------------- mma.sync helper (sm_80+, works on compute_103 PTX) ----------------
__device__ __forceinline__ void mma16816(float* c, const uint32_t* a, const uint32_t* b) {
    asm volatile(
        "mma.sync.aligned.m16n8k16.row.col.f32.bf16.bf16.f32 "
        "{%0,%1,%2,%3}, {%4,%5,%6,%7}, {%8,%9}, {%0,%1,%2,%3};"
        : "+f"(c[0]), "+f"(c[1]), "+f"(c[2]), "+f"(c[3])
        : "r"(a[0]), "r"(a[1]), "r"(a[2]), "r"(a[3]), "r"(b[0]), "r"(b[1]));
}
__device__ __forceinline__ uint32_t smem_u32(const void* p) {
    uint32_t a;
    asm("{ .reg .u64 t; cvta.to.shared.u64 t, %1; cvt.u32.u64 %0, t; }" : "=r"(a) : "l"(p));
    return a;
}

// ---------------- kernels ----------------
// Launch #1: per-(batch,chunk) group histogram
__global__ void __launch_bounds__(128) k_hist_chunk(const void* __restrict__ gt,
                                                    const void* __restrict__ fg) {
    int b = blockIdx.y, ch = blockIdx.x, t = threadIdx.x;
    __shared__ int h[Gn];
    __shared__ int fl[2];
    detect_warp(gt, fg, t, fl);
    if (t < Gn) h[t] = 0;
    __syncthreads();
    int gt64 = fl[0], fg32 = fl[1];
    int j = ch * 128 + t;
    if (get_fg(fg, b * Nn + j, fg32)) atomicAdd(&h[get_gt(gt, b * Nn + j, gt64)], 1);
    __syncthreads();
    if (t < Gn) g_ccnt[b][ch][t] = h[t];
}

// Launch #2: prefix scans + accumulator init
__global__ void __launch_bounds__(128) k_scan() {
    int t = threadIdx.x;
    if (t == 0) { g_sum = 0.0; g_num = 0; g_done = 0; }
    if (t < Bn * Gn) {
        int b = t / Gn, g = t % Gn, run = 0;
        for (int ch = 0; ch < NCH; ch++) { g_cbase[b][ch][g] = run; run += g_ccnt[b][ch][g]; }
        g_cnt[b][g] = run;
    }
    __syncthreads();
    if (t < Bn) {
        int b = t, acc = 0;
        for (int g = 0; g < Gn; g++) { g_offs[b][g] = acc; acc += g_cnt[b][g]; }
        g_offs[b][Gn] = acc;
    }
    __syncthreads();
    if (t < Bn * Gn) {
        int b = t / Gn, g = t % Gn, o = g_offs[b][g];
        for (int ch = 0; ch < NCH; ch++) g_cbase[b][ch][g] += o;
    }
}

// Launch #3: placement + normalization + bf16 hi/lo extended-vector build
__global__ void __launch_bounds__(128) k_place(const float* __restrict__ pred,
                                               const void* __restrict__ gt,
                                               const void* __restrict__ fg) {
    int b = blockIdx.y, ch = blockIdx.x, t = threadIdx.x;
    __shared__ signed char sgrp[128];
    __shared__ int fl[2];
    detect_warp(gt, fg, t, fl);
    __syncthreads();
    int gt64 = fl[0], fg32 = fl[1];
    int j = ch * 128 + t;
    bool m = get_fg(fg, b * Nn + j, fg32);
    int gv = m ? get_gt(gt, b * Nn + j, gt64) : -1;
    sgrp[t] = (signed char)gv;
    __syncthreads();
    if (!m) return;
    int r = 0;
    for (int t2 = 0; t2 < t; t2++) r += (sgrp[t2] == gv);
    int pos = g_cbase[b][ch][gv] + r;
    g_mgrp[b * Nn + pos] = (unsigned char)gv;
    g_slot[b * Nn + j] = pos;

    const float4* s = (const float4*)(pred + ((size_t)b * Nn + j) * Dn);
    float f[Dn];
    float ss = 0.f;
#pragma unroll
    for (int c = 0; c < 8; c++) {
        float4 v = s[c];
        f[4 * c] = v.x; f[4 * c + 1] = v.y; f[4 * c + 2] = v.z; f[4 * c + 3] = v.w;
        ss += v.x * v.x + v.y * v.y + v.z * v.z + v.w * v.w;
    }
    float inv = 1.0f / fmaxf(sqrtf(ss), EPSf);
#pragma unroll
    for (int c = 0; c < Dn; c++) f[c] *= inv;
    float4* d = (float4*)(g_mcoeff + ((size_t)b * Nn + pos) * Dn);
#pragma unroll
    for (int c = 0; c < 8; c++)
        d[c] = make_float4(f[4 * c], f[4 * c + 1], f[4 * c + 2], f[4 * c + 3]);

    uint32_t hi[16], lo[16];
#pragma unroll
    for (int c = 0; c < 16; c++) {
        float a0 = f[2 * c], a1 = f[2 * c + 1];
        __nv_bfloat162 h2 = __floats2bfloat162_rn(a0, a1);
        float l0 = a0 - __bfloat162float(h2.x);
        float l1 = a1 - __bfloat162float(h2.y);
        __nv_bfloat162 l2 = __floats2bfloat162_rn(l0, l1);
        hi[c] = *(uint32_t*)&h2;
        lo[c] = *(uint32_t*)&l2;
    }
    uint32_t* ea = g_ea + ((size_t)b * Nn + pos) * 48;
    uint32_t* eb = (uint32_t*)(g_eb4 + ((size_t)b * Nn + pos) * 12);
#pragma unroll
    for (int c = 0; c < 16; c++) {
        ea[c] = hi[c]; ea[16 + c] = hi[c]; ea[32 + c] = lo[c];   // A-ext: hi|hi|lo
        eb[c] = hi[c]; eb[16 + c] = lo[c]; eb[32 + c] = hi[c];   // B-ext: hi|lo|hi
    }
}

// Launch #4 (ncu-profiled): HMMA negmax. Grid (Nn/MT, Bn, NSPLIT), 128 threads.
// dot(A-ext, B-ext) over K=96 = hi*hi + hi*lo + lo*hi ≈ fp32 dot (err ~2e-5).
__global__ void __launch_bounds__(128) k_negmax() {
    extern __shared__ char smem[];
    const int b = blockIdx.y;
    const int A = g_offs[b][Gn];
    const int mbase = blockIdx.x * MT;
    if (mbase >= A) return;
    const int z = blockIdx.z;
    const int tid = threadIdx.x;
    const int wid = tid >> 5, lane = tid & 31;
    const int q = lane >> 2, t4 = lane & 3;
    const int m0 = mbase + wid * 16;
    const int r0 = m0 + q, r1 = r0 + 8;
    const size_t bNn = (size_t)b * Nn;

    // A fragments: 6 ksteps x 4 regs, loaded once from global.
    // a0=(r0,klo) a1=(r1,klo) a2=(r0,khi) a3=(r1,khi); klo=16s+2*t4, khi=+8.
    uint32_t a[6][4];
    {
        const uint32_t* ea0 = g_ea + (bNn + r0) * 48 + t4;
        const uint32_t* ea1 = g_ea + (bNn + r1) * 48 + t4;
#pragma unroll
        for (int s = 0; s < 6; s++) {
            a[s][0] = ea0[s * 8];
            a[s][1] = ea1[s * 8];
            a[s][2] = ea0[s * 8 + 4];
            a[s][3] = ea1[s * 8 + 4];
        }
    }
    int gi0 = (r0 < A) ? (int)g_mgrp[bNn + r0] : 0;
    int gi1 = (r1 < A) ? (int)g_mgrp[bNn + r1] : 0;
    int lo0 = g_offs[b][gi0], hi0 = g_offs[b][gi0 + 1];
    int lo1 = g_offs[b][gi1], hi1 = g_offs[b][gi1 + 1];
    float nm0 = -1e30f, nm1 = -1e30f;

    const uint32_t sbase = smem_u32(smem);
    const int ntiles = (A + NT - 1) / NT;
    for (int it = z; it < ntiles; it += NSPLIT) {
        __syncthreads();
        // stage tile: NT rows x 192B at 208B stride
        const uint4* src = g_eb4 + (bNn + (size_t)it * NT) * 12;
        for (int idx = tid; idx < NT * 12; idx += 128) {
            int row = idx / 12, c = idx - row * 12;
            *(uint4*)(smem + row * BSTRIDE + c * 16) = src[idx];
        }
        __syncthreads();

#pragma unroll 1
        for (int chk = 0; chk < NT / 8; chk++) {
            const int nbl = chk * 8;
            uint32_t baddr = sbase + (uint32_t)((nbl + q) * BSTRIDE + 4 * t4);
            uint32_t bb[6][2];
#pragma unroll
            for (int s = 0; s < 6; s++) {
                asm volatile("ld.shared.b32 %0, [%1];" : "=r"(bb[s][0]) : "r"(baddr + 32u * s));
                asm volatile("ld.shared.b32 %0, [%1];" : "=r"(bb[s][1]) : "r"(baddr + 32u * s + 16u));
            }
            float cA[4] = {0.f, 0.f, 0.f, 0.f};
            float cB[4] = {0.f, 0.f, 0.f, 0.f};
            mma16816(cA, a[0], bb[0]);
            mma16816(cB, a[1], bb[1]);
            mma16816(cA, a[2], bb[2]);
            mma16816(cB, a[3], bb[3]);
            mma16816(cA, a[4], bb[4]);
            mma16816(cB, a[5], bb[5]);
            int cd0 = it * NT + nbl + 2 * t4, cd1 = cd0 + 1;
            float v0 = cA[0] + cB[0], v1 = cA[1] + cB[1];
            float v2 = cA[2] + cB[2], v3 = cA[3] + cB[3];
            if (cd0 < A && (cd0 < lo0 || cd0 >= hi0)) nm0 = fmaxf(nm0, v0);
            if (cd1 < A && (cd1 < lo0 || cd1 >= hi0)) nm0 = fmaxf(nm0, v1);
            if (cd0 < A && (cd0 < lo1 || cd0 >= hi1)) nm1 = fmaxf(nm1, v2);
            if (cd1 < A && (cd1 < lo1 || cd1 >= hi1)) nm1 = fmaxf(nm1, v3);
        }
    }

    nm0 = fmaxf(nm0, __shfl_xor_sync(0xffffffffu, nm0, 1));
    nm0 = fmaxf(nm0, __shfl_xor_sync(0xffffffffu, nm0, 2));
    nm1 = fmaxf(nm1, __shfl_xor_sync(0xffffffffu, nm1, 1));
    nm1 = fmaxf(nm1, __shfl_xor_sync(0xffffffffu, nm1, 2));
    if (t4 == 0) {
        if (r0 < A) g_negS[z][bNn + r0] = nm0;
        if (r1 < A) g_negS[z][bNn + r1] = nm1;
    }
}

// Launch #5: triplet loss + block reduction + fused finalize (last block writes out)
__global__ void __launch_bounds__(256) k_loss(const float* __restrict__ posr,
                                              const void* __restrict__ gt,
                                              const void* __restrict__ fg,
                                              float* __restrict__ out, int out_size) {
    __shared__ int fl[2];
    detect_warp(gt, fg, threadIdx.x, fl);
    __syncthreads();
    int gt64 = fl[0], fg32 = fl[1];

    int i = blockIdx.x * blockDim.x + threadIdx.x;
    float per = 0.f;
    int cntv = 0;
    if (i < Bn * Nn && get_fg(fg, i, fg32)) {
        int b = i / Nn;
        int g = get_gt(gt, i, gt64);
        int cnt = g_cnt[b][g];
        int np = cnt - 1;
        int A = g_offs[b][Gn];
        if (np >= 1 && (A - cnt) > 0) {
            int slot = g_slot[i];
            int base = g_offs[b][g];
            int p = slot - base;

            float u = posr[i];
            int k = (int)floorf(u * (float)np);
            k = min(max(k, 0), np - 1);
            int sl = (k < p) ? k : k + 1;   // skip self in ordered group list
            int jslot = base + sl;

            const float* ci = g_mcoeff + ((size_t)b * Nn + slot) * Dn;
            const float* cp = g_mcoeff + ((size_t)b * Nn + jslot) * Dn;
            float ss = 0.f;
#pragma unroll
            for (int c = 0; c < Dn; c++) {
                float dd = ci[c] - cp[c];
                ss = fmaf(dd, dd, ss);
            }
            float pos_d = sqrtf(ss + EPSf);

            float s = g_negS[0][(size_t)b * Nn + slot];
#pragma unroll
            for (int zz = 1; zz < NSPLIT; zz++)
                s = fmaxf(s, g_negS[zz][(size_t)b * Nn + slot]);
            float nd2 = 2.0f - 2.0f * s;
            if (nd2 < 0.f) nd2 = 0.f;
            float neg_d = sqrtf(nd2 + EPSf);

            per = pos_d - neg_d + MARGINf;
            if (per < 0.f) per = 0.f;
            cntv = 1;
        }
    }
    double pv = (double)per;
#pragma unroll
    for (int o = 16; o > 0; o >>= 1) {
        pv   += __shfl_down_sync(0xffffffffu, pv, o);
        cntv += __shfl_down_sync(0xffffffffu, cntv, o);
    }
    __shared__ double sp[8];
    __shared__ int    sn[8];
    int w = threadIdx.x >> 5, l = threadIdx.x & 31;
    if (l == 0) { sp[w] = pv; sn[w] = cntv; }
    __syncthreads();
    if (w == 0) {
        double v = (l < 8) ? sp[l] : 0.0;
        int    n = (l < 8) ? sn[l] : 0;
#pragma unroll
        for (int o = 4; o > 0; o >>= 1) {
            v += __shfl_down_sync(0xffffffffu, v, o);
            n += __shfl_down_sync(0xffffffffu, n, o);
        }
        if (l == 0) {
            if (v != 0.0 || n != 0) {
                atomicAdd(&g_sum, v);
                atomicAdd(&g_num, n);
            }
            __threadfence();
            int prev = atomicAdd(&g_done, 1);
            if (prev == (int)gridDim.x - 1) {
                double fs = atomicAdd(&g_sum, 0.0);   // ordered read-back
                int    fn = atomicAdd(&g_num, 0);
                float val = (fn > 0) ? (float)(fs / (double)fn) : 0.0f;
                for (int o2 = 0; o2 < out_size; o2++) out[o2] = (o2 == 0) ? val : 0.0f;
            }
        }
    }
}

// ---------------- launch ----------------
extern "C" void kernel_launch(void* const* d_in, const int* in_sizes, int n_in,
                              void* d_out, int out_size) {
    const float* pred = (const float*)d_in[0];
    const float* posr = (const float*)d_in[1];
    const void*  gt   = (const void*)d_in[2];
    const void*  fg   = (const void*)d_in[3];
    float* out = (float*)d_out;

    dim3 gc(NCH, Bn);
    k_hist_chunk<<<gc, 128>>>(gt, fg);
    k_scan<<<1, 128>>>();
    k_place<<<gc, 128>>>(pred, gt, fg);
    dim3 gn(Nn / MT, Bn, NSPLIT);
    k_negmax<<<gn, 128, SMEM_NEG>>>();
    k_loss<<<(Bn * Nn + 255) / 256, 256>>>(posr, gt, fg, out, out_size);
}